// round 15
// baseline (speedup 1.0000x reference)
#include <cuda_runtime.h>
#include <math.h>

// ---------------- problem constants ----------------
#define NB   16
#define DLEN 64
#define PLEN 1200
#define D1L  61
#define D2L  56
#define D3L  49
#define P1L  1197
#define P2L  1190
#define P3L  1179
#define C1   40
#define C2   80
#define C3   160

typedef unsigned long long u64;

// ---------------- scratch (device globals; no allocs allowed) ----------------
__device__ float g_d1[NB * C1 * D1L];
__device__ float g_d2[NB * C2 * D2L];
__device__ float g_dc[NB * C3 * D3L];
__device__ float g_p1[NB * C1 * P1L];
__device__ float g_p2[NB * C2 * P2L];
__device__ float g_pc[NB * C3 * P3L];
__device__ float g_datt[NB * C3 * D3L];
__device__ float g_patt[NB * C3 * P3L];
__device__ float g_Sd[NB * C3 * D3L];
__device__ float g_Sp[NB * C3 * P3L];
__device__ float g_pair[NB * 320];

// ---------------- f32x2 packed helpers ----------------
__device__ __forceinline__ u64 pack2(float lo, float hi) {
    u64 d;
    asm("mov.b64 %0, {%1, %2};" : "=l"(d) : "r"(__float_as_uint(lo)), "r"(__float_as_uint(hi)));
    return d;
}
__device__ __forceinline__ void unpack2(float& lo, float& hi, u64 v) {
    unsigned int a, b;
    asm("mov.b64 {%0, %1}, %2;" : "=r"(a), "=r"(b) : "l"(v));
    lo = __uint_as_float(a); hi = __uint_as_float(b);
}
__device__ __forceinline__ void fma2(u64& d, u64 a, u64 b) {
    asm("fma.rn.f32x2 %0, %1, %2, %3;" : "=l"(d) : "l"(a), "l"(b), "l"(d));
}

// ---------------- cp.async helpers ----------------
__device__ __forceinline__ void cp4(float* s, const float* g) {
    unsigned a = (unsigned)__cvta_generic_to_shared(s);
    asm volatile("cp.async.ca.shared.global [%0], [%1], 4;" :: "r"(a), "l"(g) : "memory");
}
__device__ __forceinline__ void cp_commit() {
    asm volatile("cp.async.commit_group;" ::: "memory");
}
__device__ __forceinline__ void cp_wait1() {
    asm volatile("cp.async.wait_group 1;" ::: "memory");
}
__device__ __forceinline__ void cp_wait0() {
    asm volatile("cp.async.wait_group 0;" ::: "memory");
}

// ---------------- conv config ----------------
// PIPE: 1 = cp.async double-buffer (in+w per chunk; supports EMB),
//       2 = cp.async double-buffer input, weights staged once (K==1)
// EPI: 0 relu, 1 linear, 2 sigmoid(scale*acc+bias),
//      3 = fused sigmoid-gate-maxpool (no store; atomicMax into pool_out)
template <int K_, int CIN_, int CH_, int TL_, int T_, int TO_, int OTT_, int EPI_, int EMB_, int PIPE_>
struct CC {
    static constexpr int K = K_, CIN = CIN_, CH = CH_, TILE_L = TL_, T = T_, TILE_O = TO_;
    static constexpr int OTT = OTT_, EPI = EPI_, EMB = EMB_, PIPE = PIPE_;
    static constexpr int LT = TL_ / T_, OT = TO_ / OTT_, NACC = OTT_ / 2;
    static constexpr int NTHR = LT * OT;
    static constexpr int NWIN = T_ + K_ - 1;
    static constexpr int NW4 = (NWIN + 3) / 4;
    static constexpr int PITCH = TL_ + 4 * NW4;
    static constexpr int WV = TL_ + K_ - 1;
    static constexpr int TOP = TO_ + 2;                 // padded weight pitch (even)
    static constexpr int NCH = CIN_ / CH_;
    static constexpr int CHUNKF = CH_ * PITCH + (PIPE_ == 1 ? CH_ * K_ * TOP : 0);
    static constexpr int SMEMF = 2 * CHUNKF + (PIPE_ == 2 ? CIN_ * TOP : 0)
                               + (EMB_ ? (TL_ + 32) : 0);
};

// ---------------- compute core over one CH-chunk ----------------
template <class C>
__device__ __forceinline__ void conv_compute(
    const float* __restrict__ inS, const float* __restrict__ wS, int wpitch,
    u64 (&accp)[C::NACC][C::T], int lbase, int oy)
{
    constexpr int K = C::K, CH = C::CH, T = C::T, OTT = C::OTT;
    constexpr int NACC = C::NACC, NWIN = C::NWIN, NW4 = C::NW4, PITCH = C::PITCH;
#pragma unroll 2
    for (int i2 = 0; i2 < CH; i2++) {
        float win[NW4 * 4];
#pragma unroll
        for (int n = 0; n < NW4; n++) {
            float4 v = *(const float4*)&inS[i2 * PITCH + lbase + 4 * n];
            win[4 * n + 0] = v.x; win[4 * n + 1] = v.y;
            win[4 * n + 2] = v.z; win[4 * n + 3] = v.w;
        }
        u64 wdup[NWIN];
#pragma unroll
        for (int j = 0; j < NWIN; j++) wdup[j] = pack2(win[j], win[j]);
#pragma unroll
        for (int k = 0; k < K; k++) {
            const u64* wrow = (const u64*)&wS[(i2 * K + k) * wpitch + oy * OTT];
            u64 wp[NACC];
#pragma unroll
            for (int p = 0; p < NACC; p++) wp[p] = wrow[p];
#pragma unroll
            for (int t = 0; t < T; t++)
#pragma unroll
                for (int p = 0; p < NACC; p++)
                    fma2(accp[p][t], wp[p], wdup[k + t]);
        }
    }
}

// ---------------- chunk preload via cp.async ----------------
template <class C>
__device__ __forceinline__ void conv_preload(
    float* __restrict__ buf, const float* __restrict__ in, const int* __restrict__ tokS,
    const float* __restrict__ W,
    int ch, int b, int l0, int o0, int Lin, int tid, int BT)
{
    constexpr int K = C::K, CIN = C::CIN, CH = C::CH, TO = C::TILE_O, TOP = C::TOP;
    constexpr int PITCH = C::PITCH, WV = C::WV;
    const int ci0 = ch * CH;
    for (int idx = tid; idx < CH * WV; idx += BT) {
        int i2 = idx / WV, j = idx - i2 * WV;
        int gl = l0 + j;
        float* d = &buf[i2 * PITCH + j];
        if (C::EMB) {
            if (gl < Lin) cp4(d, &in[tokS[j] * 64 + (ci0 + i2)]);
            else *d = 0.f;
        } else {
            if (gl < Lin) cp4(d, &in[((size_t)b * CIN + ci0 + i2) * Lin + gl]);
            else *d = 0.f;
        }
    }
    if (C::PIPE == 1) {
        float* bw = buf + CH * PITCH;
        for (int idx = tid; idx < TO * CH * K; idx += BT) {
            int oo = idx / (CH * K), j = idx - oo * (CH * K);
            cp4(&bw[j * TOP + oo], &W[(size_t)(o0 + oo) * CIN * K + ci0 * K + j]);
        }
    }
}

// ---------------- conv body ----------------
template <class C>
__device__ __forceinline__ void conv_body(
    float* __restrict__ sm,
    const float* __restrict__ in, const int* __restrict__ tok,
    const float* __restrict__ W, const float* __restrict__ bias,
    float* __restrict__ out, const float* __restrict__ gate, int poff,
    int Lin, int Lout, int Cout, float scale,
    int bx, int by, int bz, int BT)
{
    constexpr int K = C::K, CIN = C::CIN, CH = C::CH;
    constexpr int TILE_L = C::TILE_L, T = C::T, TILE_O = C::TILE_O, OTT = C::OTT;
    constexpr int LT = C::LT, NACC = C::NACC, NTHR = C::NTHR;
    constexpr int PITCH = C::PITCH, WV = C::WV;
    constexpr int TOP = C::TOP, NCH = C::NCH, CHUNKF = C::CHUNKF;

    const int b = bz, o0 = by * TILE_O, l0 = bx * TILE_L;
    const int tid = threadIdx.x;
    const int lx = tid % LT, oy = tid / LT;
    const int lbase = lx * T;
    const bool act = tid < NTHR;

    u64 accp[NACC][T];
#pragma unroll
    for (int p = 0; p < NACC; p++)
#pragma unroll
        for (int t = 0; t < T; t++) {
            if (C::EPI >= 2) accp[p][t] = 0ull;
            else accp[p][t] = pack2(bias[o0 + oy * OTT + 2 * p],
                                    bias[o0 + oy * OTT + 2 * p + 1]);
        }

    float* wFull = sm + 2 * CHUNKF;                    // PIPE==2
    int* tokS = (int*)(sm + 2 * CHUNKF + (C::PIPE == 2 ? CIN * TOP : 0));  // EMB

    if (C::EMB) {
        for (int idx = tid; idx < WV; idx += BT) {
            int gl = l0 + idx;
            tokS[idx] = (gl < Lin) ? tok[b * Lin + gl] : 0;
        }
        __syncthreads();
    }
    if (C::PIPE == 2) {
        for (int idx = tid; idx < CIN * TILE_O; idx += BT) {
            int o = idx / CIN, c = idx - o * CIN;
            wFull[c * TOP + o] = W[(size_t)(o0 + o) * CIN + c];
        }
    }

    conv_preload<C>(sm, in, tokS, W, 0, b, l0, o0, Lin, tid, BT);
    cp_commit();
    for (int ch = 0; ch < NCH; ch++) {
        float* cur = sm + (ch & 1) * CHUNKF;
        if (ch + 1 < NCH) {
            conv_preload<C>(sm + ((ch + 1) & 1) * CHUNKF, in, tokS, W, ch + 1, b, l0, o0, Lin, tid, BT);
            cp_commit();
            cp_wait1();
        } else {
            cp_wait0();
        }
        __syncthreads();
        if (act) {
            if (C::PIPE == 1)
                conv_compute<C>(cur, cur + CH * PITCH, TOP, accp, lbase, oy);
            else
                conv_compute<C>(cur, wFull + ch * CH * K * TOP, TOP, accp, lbase, oy);
        }
        __syncthreads();
    }

    if (act) {
#pragma unroll
        for (int p = 0; p < NACC; p++) {
            int olo = o0 + oy * OTT + 2 * p;
            if (C::EPI == 3) {
                // fused sigmoid-gate-maxpool: no store of attention map
                float m0 = 0.f, m1 = 0.f;
                const float* g0 = gate + ((size_t)b * Cout + olo) * Lout;
                const float* g1 = g0 + Lout;
#pragma unroll
                for (int t = 0; t < T; t++) {
                    int l = l0 + lbase + t;
                    if (l >= Lout) continue;
                    float vlo, vhi;
                    unpack2(vlo, vhi, accp[p][t]);
                    vlo = 1.f / (1.f + __expf(-(vlo * scale + bias[olo])));
                    vhi = 1.f / (1.f + __expf(-(vhi * scale + bias[olo + 1])));
                    m0 = fmaxf(m0, g0[l] * (0.5f + vlo));
                    m1 = fmaxf(m1, g1[l] * (0.5f + vhi));
                }
#pragma unroll
                for (int s = LT / 2; s; s >>= 1) {
                    m0 = fmaxf(m0, __shfl_xor_sync(0xffffffffu, m0, s));
                    m1 = fmaxf(m1, __shfl_xor_sync(0xffffffffu, m1, s));
                }
                if (lx == 0) {
                    atomicMax((int*)&out[b * 320 + poff + olo], __float_as_int(m0));
                    atomicMax((int*)&out[b * 320 + poff + olo + 1], __float_as_int(m1));
                }
            } else {
#pragma unroll
                for (int t = 0; t < T; t++) {
                    int l = l0 + lbase + t;
                    if (l >= Lout) continue;
                    float vlo, vhi;
                    unpack2(vlo, vhi, accp[p][t]);
                    if (C::EPI == 0) { vlo = fmaxf(vlo, 0.f); vhi = fmaxf(vhi, 0.f); }
                    else if (C::EPI == 2) {
                        vlo = 1.f / (1.f + __expf(-(vlo * scale + bias[olo])));
                        vhi = 1.f / (1.f + __expf(-(vhi * scale + bias[olo + 1])));
                    }
                    out[((size_t)b * Cout + olo) * Lout + l] = vlo;
                    out[((size_t)b * Cout + olo + 1) * Lout + l] = vhi;
                }
            }
        }
    }
}

// ---------------- dual conv kernel (protein blocks first, then drug blocks) ----------------
template <class CP, class CD>
__global__ void __launch_bounds__(128)
dual_conv(const float* __restrict__ inP, const int* __restrict__ tokP,
          const float* __restrict__ WP, const float* __restrict__ bP, float* __restrict__ outP,
          const float* __restrict__ gateP,
          int LinP, int LoutP, float scP, int gxP, int gyP,
          const float* __restrict__ inD, const int* __restrict__ tokD,
          const float* __restrict__ WD, const float* __restrict__ bD, float* __restrict__ outD,
          const float* __restrict__ gateD,
          int LinD, int LoutD, float scD, int gxD, int gyD)
{
    constexpr int SMF = CP::SMEMF > CD::SMEMF ? CP::SMEMF : CD::SMEMF;
    __shared__ __align__(16) float sm[SMF];
    int blk = blockIdx.x;
    int nP = gxP * gyP * NB;
    if (blk < nP) {
        int bx = blk % gxP; int r = blk / gxP;
        int by = r % gyP, bz = r / gyP;
        conv_body<CP>(sm, inP, tokP, WP, bP, outP, gateP, 160, LinP, LoutP, gyP * CP::TILE_O,
                      scP, bx, by, bz, blockDim.x);
    } else {
        blk -= nP;
        int bx = blk % gxD; int r = blk / gxD;
        int by = r % gyD, bz = r / gyD;
        conv_body<CD>(sm, inD, tokD, WD, bD, outD, gateD, 0, LinD, LoutD, gyD * CD::TILE_O,
                      scD, bx, by, bz, blockDim.x);
    }
}

// ---------------- interaction sums ----------------
__global__ void interact_kernel(const float* __restrict__ datt, const float* __restrict__ patt,
                                float* __restrict__ Sd, float* __restrict__ Sp)
{
    int k = blockIdx.x, b = blockIdx.y;
    int t = threadIdx.x;
    __shared__ float dvs[D3L];
    __shared__ float red[8][D3L];

    const float* dv = datt + ((size_t)b * C3 + k) * D3L;
    const float* pv = patt + ((size_t)b * C3 + k) * P3L;
    float* SpRow = Sp + ((size_t)b * C3 + k) * P3L;

    if (t < D3L) dvs[t] = dv[t];
    __syncthreads();

    float dl[D3L];
#pragma unroll
    for (int d = 0; d < D3L; d++) dl[d] = dvs[d];
    float sdp[D3L];
#pragma unroll
    for (int d = 0; d < D3L; d++) sdp[d] = 0.f;

    for (int p = t; p < P3L; p += 256) {
        float pvv = pv[p];
        float sp = 0.f;
#pragma unroll
        for (int d = 0; d < D3L; d++) {
            float v = fmaxf(dl[d] + pvv, 0.f);
            sdp[d] += v;
            sp += v;
        }
        SpRow[p] = sp;
    }

    int warp = t >> 5, lane = t & 31;
#pragma unroll
    for (int d = 0; d < D3L; d++) {
        float v = sdp[d];
        v += __shfl_xor_sync(0xffffffffu, v, 16);
        v += __shfl_xor_sync(0xffffffffu, v, 8);
        v += __shfl_xor_sync(0xffffffffu, v, 4);
        v += __shfl_xor_sync(0xffffffffu, v, 2);
        v += __shfl_xor_sync(0xffffffffu, v, 1);
        if (lane == 0) red[warp][d] = v;
    }
    __syncthreads();
    if (t < D3L) {
        float s = 0.f;
#pragma unroll
        for (int w = 0; w < 8; w++) s += red[w][t];
        Sd[((size_t)b * C3 + k) * D3L + t] = s;
    }
}

// ---------------- fused 4-layer MLP head ----------------
__global__ void __launch_bounds__(1024)
mlp_kernel(const float* __restrict__ pairv,
           const float* __restrict__ fc1W, const float* __restrict__ fc1b,
           const float* __restrict__ fc2W, const float* __restrict__ fc2b,
           const float* __restrict__ fc3W, const float* __restrict__ fc3b,
           const float* __restrict__ outW, const float* __restrict__ outb,
           float* __restrict__ out)
{
    __shared__ float s0[320];
    __shared__ float h1s[1024];
    __shared__ float h2s[1024];
    __shared__ float h3s[512];
    int b = blockIdx.x, t = threadIdx.x;

    if (t < 320) s0[t] = pairv[b * 320 + t];
    __syncthreads();

    {
        const float4* Wo = (const float4*)(fc1W + (size_t)t * 320);
        float acc = fc1b[t];
#pragma unroll 8
        for (int i = 0; i < 80; i++) {
            float4 wv = Wo[i];
            const float* xv = &s0[4 * i];
            acc = fmaf(wv.x, xv[0], acc);
            acc = fmaf(wv.y, xv[1], acc);
            acc = fmaf(wv.z, xv[2], acc);
            acc = fmaf(wv.w, xv[3], acc);
        }
        h1s[t] = acc > 0.f ? acc : 0.01f * acc;
    }
    __syncthreads();

    {
        const float4* Wo = (const float4*)(fc2W + (size_t)t * 1024);
        float acc = fc2b[t];
#pragma unroll 8
        for (int i = 0; i < 256; i++) {
            float4 wv = Wo[i];
            const float* xv = &h1s[4 * i];
            acc = fmaf(wv.x, xv[0], acc);
            acc = fmaf(wv.y, xv[1], acc);
            acc = fmaf(wv.z, xv[2], acc);
            acc = fmaf(wv.w, xv[3], acc);
        }
        h2s[t] = acc > 0.f ? acc : 0.01f * acc;
    }
    __syncthreads();

    if (t < 512) {
        const float4* Wo = (const float4*)(fc3W + (size_t)t * 1024);
        float acc = fc3b[t];
#pragma unroll 8
        for (int i = 0; i < 256; i++) {
            float4 wv = Wo[i];
            const float* xv = &h2s[4 * i];
            acc = fmaf(wv.x, xv[0], acc);
            acc = fmaf(wv.y, xv[1], acc);
            acc = fmaf(wv.z, xv[2], acc);
            acc = fmaf(wv.w, xv[3], acc);
        }
        h3s[t] = acc > 0.f ? acc : 0.01f * acc;
    }
    __syncthreads();

    if (t < 64) {
        int o = t >> 5, lane = t & 31;
        const float* Wo = outW + (size_t)o * 512;
        float acc = 0.f;
#pragma unroll
        for (int i = 0; i < 16; i++)
            acc = fmaf(Wo[lane + 32 * i], h3s[lane + 32 * i], acc);
#pragma unroll
        for (int s = 16; s; s >>= 1)
            acc += __shfl_xor_sync(0xffffffffu, acc, s);
        if (lane == 0) out[b * 2 + o] = acc + outb[o];
    }
}

// ---------------- configs:  K, CIN, CH, TL, T, TO, OTT, EPI, EMB, PIPE ----------------
using CP1 = CC<4, 64, 16, 128, 4, 8, 2, 0, 1, 1>;   // protein conv1 (+emb), pipelined
using CD1 = CC<4, 64, 16, 64, 4, 8, 2, 0, 1, 1>;    // drug conv1 (+emb), pipelined
using CP2 = CC<8, 40, 8, 128, 4, 16, 4, 0, 0, 1>;   // protein conv2
using CD2 = CC<6, 40, 8, 64, 4, 16, 4, 0, 0, 1>;    // drug conv2
using CP3 = CC<12, 80, 8, 128, 4, 16, 4, 0, 0, 1>;  // protein conv3
using CD3 = CC<8, 80, 8, 64, 4, 16, 4, 0, 0, 1>;    // drug conv3
using CPp = CC<1, 160, 16, 128, 4, 16, 4, 1, 0, 2>; // protein proj
using CDp = CC<1, 160, 16, 64, 4, 16, 4, 1, 0, 2>;  // drug proj
using CPa = CC<1, 160, 16, 128, 4, 16, 4, 3, 0, 2>; // protein att_out+gate+pool (fused)
using CDa = CC<1, 160, 16, 64, 4, 16, 4, 3, 0, 2>;  // drug att_out+gate+pool (fused)

// ---------------- launch ----------------
extern "C" void kernel_launch(void* const* d_in, const int* in_sizes, int n_in,
                              void* d_out, int out_size)
{
    const int*   dtok = (const int*)d_in[0];
    const int*   ptok = (const int*)d_in[1];
    const float* demb = (const float*)d_in[2];
    const float* pemb = (const float*)d_in[3];
    const float* dW1 = (const float*)d_in[4],  *db1 = (const float*)d_in[5];
    const float* dW2 = (const float*)d_in[6],  *db2 = (const float*)d_in[7];
    const float* dW3 = (const float*)d_in[8],  *db3 = (const float*)d_in[9];
    const float* pW1 = (const float*)d_in[10], *pb1 = (const float*)d_in[11];
    const float* pW2 = (const float*)d_in[12], *pb2 = (const float*)d_in[13];
    const float* pW3 = (const float*)d_in[14], *pb3 = (const float*)d_in[15];
    const float* dattW = (const float*)d_in[16], *dattb = (const float*)d_in[17];
    const float* pattW = (const float*)d_in[18], *pattb = (const float*)d_in[19];
    const float* attW  = (const float*)d_in[20], *attb  = (const float*)d_in[21];
    const float* fc1W = (const float*)d_in[22], *fc1b = (const float*)d_in[23];
    const float* fc2W = (const float*)d_in[24], *fc2b = (const float*)d_in[25];
    const float* fc3W = (const float*)d_in[26], *fc3b = (const float*)d_in[27];
    const float* outW = (const float*)d_in[28], *outb = (const float*)d_in[29];
    float* out = (float*)d_out;

    float *d1, *d2, *dc, *p1, *p2, *pc;
    float *datt, *patt, *Sd, *Sp, *pairv;
    cudaGetSymbolAddress((void**)&d1, g_d1);
    cudaGetSymbolAddress((void**)&d2, g_d2);
    cudaGetSymbolAddress((void**)&dc, g_dc);
    cudaGetSymbolAddress((void**)&p1, g_p1);
    cudaGetSymbolAddress((void**)&p2, g_p2);
    cudaGetSymbolAddress((void**)&pc, g_pc);
    cudaGetSymbolAddress((void**)&datt, g_datt);
    cudaGetSymbolAddress((void**)&patt, g_patt);
    cudaGetSymbolAddress((void**)&Sd, g_Sd);
    cudaGetSymbolAddress((void**)&Sp, g_Sp);
    cudaGetSymbolAddress((void**)&pairv, g_pair);

    // conv1: P gx=10 (1280>=1197) gy=5 -> 800; D gx=1 gy=5 -> 80  (pipelined EMB)
    dual_conv<CP1, CD1><<<800 + 80, 128>>>(
        pemb, ptok, pW1, pb1, p1, 0, PLEN, P1L, 0.f, 10, 5,
        demb, dtok, dW1, db1, d1, 0, DLEN, D1L, 0.f, 1, 5);

    // conv2: P 800; D 80
    dual_conv<CP2, CD2><<<800 + 80, 128>>>(
        p1, 0, pW2, pb2, p2, 0, P1L, P2L, 0.f, 10, 5,
        d1, 0, dW2, db2, d2, 0, D1L, D2L, 0.f, 1, 5);

    // conv3: P gx=10 gy=10 -> 1600; D 160
    dual_conv<CP3, CD3><<<1600 + 160, 128>>>(
        p2, 0, pW3, pb3, pc, 0, P2L, P3L, 0.f, 10, 10,
        d2, 0, dW3, db3, dc, 0, D2L, D3L, 0.f, 1, 10);

    // attention projections: P 1600; D 160
    dual_conv<CPp, CDp><<<1600 + 160, 128>>>(
        pc, 0, pattW, pattb, patt, 0, P3L, P3L, 0.f, 10, 10,
        dc, 0, dattW, dattb, datt, 0, D3L, D3L, 0.f, 1, 10);

    // interaction sums
    interact_kernel<<<dim3(C3, NB), 256>>>(datt, patt, Sd, Sp);

    // zero the pooled pair vector (atomicMax target; values are >= 0)
    cudaMemsetAsync(pairv, 0, NB * 320 * sizeof(float));

    // fused attention-output + gating + max-pool: writes pairv directly
    dual_conv<CPa, CDa><<<1600 + 160, 128>>>(
        Sp, 0, attW, attb, pairv, pc, P3L, P3L, 1.f / (float)D3L, 10, 10,
        Sd, 0, attW, attb, pairv, dc, D3L, D3L, 1.f / (float)P3L, 1, 10);

    // MLP head
    mlp_kernel<<<NB, 1024>>>(pairv, fc1W, fc1b, fc2W, fc2b, fc3W, fc3b, outW, outb, out);
}

// round 17
// speedup vs baseline: 1.1204x; 1.1204x over previous
#include <cuda_runtime.h>
#include <math.h>

// ---------------- problem constants ----------------
#define NB   16
#define DLEN 64
#define PLEN 1200
#define D1L  61
#define D2L  56
#define D3L  49
#define P1L  1197
#define P2L  1190
#define P3L  1179
#define C1   40
#define C2   80
#define C3   160
// padded (16B-aligned) row pitches for intermediate buffers
#define D1P  64
#define D2P  56
#define D3P  52
#define P1P  1200
#define P2P  1192
#define P3P  1180

typedef unsigned long long u64;

// ---------------- scratch (device globals; padded rows + tail pad) ----------------
__device__ float g_d1[NB * C1 * D1P + 128];
__device__ float g_d2[NB * C2 * D2P + 128];
__device__ float g_dc[NB * C3 * D3P + 128];
__device__ float g_p1[NB * C1 * P1P + 128];
__device__ float g_p2[NB * C2 * P2P + 128];
__device__ float g_pc[NB * C3 * P3P + 128];
__device__ float g_datt[NB * C3 * D3P + 128];
__device__ float g_patt[NB * C3 * P3P + 128];
__device__ float g_Sd[NB * C3 * D3P + 128];
__device__ float g_Sp[NB * C3 * P3P + 128];
__device__ float g_pair[NB * 320];
// transposed weights: layout [c*K+k][o], contiguous per layer
#define OFF_dW1t 0
#define OFF_dW2t 10240
#define OFF_dW3t 29440
#define OFF_pW1t 131840
#define OFF_pW2t 142080
#define OFF_pW3t 167680
#define OFF_dattWt 321280
#define OFF_pattWt 346880
#define OFF_attWt 372480
__device__ float g_wt[398080];

// ---------------- f32x2 packed helpers ----------------
__device__ __forceinline__ u64 pack2(float lo, float hi) {
    u64 d;
    asm("mov.b64 %0, {%1, %2};" : "=l"(d) : "r"(__float_as_uint(lo)), "r"(__float_as_uint(hi)));
    return d;
}
__device__ __forceinline__ void unpack2(float& lo, float& hi, u64 v) {
    unsigned int a, b;
    asm("mov.b64 {%0, %1}, %2;" : "=r"(a), "=r"(b) : "l"(v));
    lo = __uint_as_float(a); hi = __uint_as_float(b);
}
__device__ __forceinline__ void fma2(u64& d, u64 a, u64 b) {
    asm("fma.rn.f32x2 %0, %1, %2, %3;" : "=l"(d) : "l"(a), "l"(b), "l"(d));
}

// ---------------- cp.async helpers ----------------
__device__ __forceinline__ void cp4(float* s, const float* g) {
    unsigned a = (unsigned)__cvta_generic_to_shared(s);
    asm volatile("cp.async.ca.shared.global [%0], [%1], 4;" :: "r"(a), "l"(g) : "memory");
}
__device__ __forceinline__ void cp16(float* s, const float* g) {
    unsigned a = (unsigned)__cvta_generic_to_shared(s);
    asm volatile("cp.async.cg.shared.global [%0], [%1], 16;" :: "r"(a), "l"(g) : "memory");
}
__device__ __forceinline__ void cp_commit() {
    asm volatile("cp.async.commit_group;" ::: "memory");
}
__device__ __forceinline__ void cp_wait1() {
    asm volatile("cp.async.wait_group 1;" ::: "memory");
}
__device__ __forceinline__ void cp_wait0() {
    asm volatile("cp.async.wait_group 0;" ::: "memory");
}

// ---------------- weight pre-transpose: Wt[(c*K+k)*Cout + o] = W[o][c][k] ----------------
__global__ void prep_w(const float* __restrict__ dW1, const float* __restrict__ dW2,
                       const float* __restrict__ dW3, const float* __restrict__ pW1,
                       const float* __restrict__ pW2, const float* __restrict__ pW3,
                       const float* __restrict__ dattW, const float* __restrict__ pattW,
                       const float* __restrict__ attW, float* __restrict__ wt)
{
    const float* src; float* dst; int Cout, CINK;
    switch (blockIdx.y) {
        case 0: src = dW1;   dst = wt + OFF_dW1t;   Cout = 40;  CINK = 256; break;
        case 1: src = dW2;   dst = wt + OFF_dW2t;   Cout = 80;  CINK = 240; break;
        case 2: src = dW3;   dst = wt + OFF_dW3t;   Cout = 160; CINK = 640; break;
        case 3: src = pW1;   dst = wt + OFF_pW1t;   Cout = 40;  CINK = 256; break;
        case 4: src = pW2;   dst = wt + OFF_pW2t;   Cout = 80;  CINK = 320; break;
        case 5: src = pW3;   dst = wt + OFF_pW3t;   Cout = 160; CINK = 960; break;
        case 6: src = dattW; dst = wt + OFF_dattWt; Cout = 160; CINK = 160; break;
        case 7: src = pattW; dst = wt + OFF_pattWt; Cout = 160; CINK = 160; break;
        default: src = attW; dst = wt + OFF_attWt;  Cout = 160; CINK = 160; break;
    }
    int n = Cout * CINK;
    for (int idx = blockIdx.x * blockDim.x + threadIdx.x; idx < n; idx += gridDim.x * blockDim.x) {
        int r = idx / Cout, o = idx - r * Cout;
        dst[idx] = src[o * CINK + r];   // write-coalesced
    }
}

// ---------------- conv config ----------------
// PIPE: 1 = double-buffer input + per-chunk weights; 2 = double-buffer input, weights once (K==1)
// EPI: 0 relu, 1 linear, 3 fused sigmoid-gate-maxpool
template <int K_, int CIN_, int CH_, int TL_, int T_, int TO_, int OTT_, int EPI_, int EMB_, int PIPE_>
struct CC {
    static constexpr int K = K_, CIN = CIN_, CH = CH_, TILE_L = TL_, T = T_, TILE_O = TO_;
    static constexpr int OTT = OTT_, EPI = EPI_, EMB = EMB_, PIPE = PIPE_;
    static constexpr int LT = TL_ / T_, OT = TO_ / OTT_, NACC = OTT_ / 2;
    static constexpr int NTHR = LT * OT;
    static constexpr int NWIN = T_ + K_ - 1;
    static constexpr int NW4 = (NWIN + 3) / 4;
    static constexpr int PITCH = TL_ + 4 * NW4;
    static constexpr int WV = TL_ + K_ - 1;
    static constexpr int WV4 = (WV + 3) / 4;
    static constexpr int TO4 = TO_ / 4;
    static constexpr int NCH = CIN_ / CH_;
    static constexpr int CHUNKF = CH_ * PITCH + (PIPE_ == 1 ? CH_ * K_ * TO_ : 0);
    static constexpr int SMEMF = 2 * CHUNKF + (PIPE_ == 2 ? CIN_ * TO_ : 0)
                               + (EMB_ ? (TL_ + 32) : 0);
};

// ---------------- compute core over one CH-chunk ----------------
template <class C>
__device__ __forceinline__ void conv_compute(
    const float* __restrict__ inS, const float* __restrict__ wS,
    u64 (&accp)[C::NACC][C::T], int lbase, int oy)
{
    constexpr int K = C::K, CH = C::CH, T = C::T, OTT = C::OTT, TO = C::TILE_O;
    constexpr int NACC = C::NACC, NWIN = C::NWIN, NW4 = C::NW4, PITCH = C::PITCH;
#pragma unroll 2
    for (int i2 = 0; i2 < CH; i2++) {
        float win[NW4 * 4];
#pragma unroll
        for (int n = 0; n < NW4; n++) {
            float4 v = *(const float4*)&inS[i2 * PITCH + lbase + 4 * n];
            win[4 * n + 0] = v.x; win[4 * n + 1] = v.y;
            win[4 * n + 2] = v.z; win[4 * n + 3] = v.w;
        }
        u64 wdup[NWIN];
#pragma unroll
        for (int j = 0; j < NWIN; j++) wdup[j] = pack2(win[j], win[j]);
#pragma unroll
        for (int k = 0; k < K; k++) {
            const u64* wrow = (const u64*)&wS[(i2 * K + k) * TO + oy * OTT];
            u64 wp[NACC];
#pragma unroll
            for (int p = 0; p < NACC; p++) wp[p] = wrow[p];
#pragma unroll
            for (int t = 0; t < T; t++)
#pragma unroll
                for (int p = 0; p < NACC; p++)
                    fma2(accp[p][t], wp[p], wdup[k + t]);
        }
    }
}

// ---------------- chunk preload via 16B cp.async (no bounds checks) ----------------
template <class C>
__device__ __forceinline__ void conv_preload(
    float* __restrict__ buf, const float* __restrict__ in, const int* __restrict__ tokS,
    const float* __restrict__ Wt,
    int ch, int b, int l0, int o0, int Lin, int LinP, int Cout, int tid, int BT)
{
    constexpr int K = C::K, CIN = C::CIN, CH = C::CH, TO = C::TILE_O, TO4 = C::TO4;
    constexpr int PITCH = C::PITCH, WV = C::WV, WV4 = C::WV4;
    const int ci0 = ch * CH;
    if (C::EMB) {
        // gather path (conv1): 4B cp with bounds
        for (int idx = tid; idx < CH * WV; idx += BT) {
            int i2 = idx / WV, j = idx - i2 * WV;
            int gl = l0 + j;
            float* d = &buf[i2 * PITCH + j];
            if (gl < Lin) cp4(d, &in[tokS[j] * 64 + (ci0 + i2)]);
            else *d = 0.f;
        }
    } else {
        const float* base = in + ((size_t)b * CIN + ci0) * LinP + l0;
        for (int idx = tid; idx < CH * WV4; idx += BT) {
            int i2 = idx / WV4, j4 = idx - i2 * WV4;
            cp16(&buf[i2 * PITCH + 4 * j4], base + (size_t)i2 * LinP + 4 * j4);
        }
    }
    if (C::PIPE == 1) {
        // transposed weights: rows (ci0*K .. ci0*K+CH*K) x Cout, take o0..o0+TO
        float* bw = buf + CH * PITCH;
        const float* wbase = Wt + (size_t)ci0 * K * Cout + o0;
        for (int idx = tid; idx < CH * K * TO4; idx += BT) {
            int r = idx / TO4, q = idx - r * TO4;
            cp16(&bw[r * TO + 4 * q], wbase + (size_t)r * Cout + 4 * q);
        }
    }
}

// ---------------- conv body ----------------
template <class C>
__device__ __forceinline__ void conv_body(
    float* __restrict__ sm,
    const float* __restrict__ in, const int* __restrict__ tok,
    const float* __restrict__ Wt, const float* __restrict__ bias,
    float* __restrict__ out, const float* __restrict__ gate, int poff,
    int Lin, int LinP, int Lout, int LoutP, int Cout, float scale,
    int bx, int by, int bz, int BT)
{
    constexpr int K = C::K, CIN = C::CIN, CH = C::CH;
    constexpr int TILE_L = C::TILE_L, T = C::T, TILE_O = C::TILE_O, OTT = C::OTT;
    constexpr int LT = C::LT, NACC = C::NACC, NTHR = C::NTHR;
    constexpr int PITCH = C::PITCH, WV = C::WV, TO4 = C::TO4;
    constexpr int NCH = C::NCH, CHUNKF = C::CHUNKF;

    const int b = bz, o0 = by * TILE_O, l0 = bx * TILE_L;
    const int tid = threadIdx.x;
    const int lx = tid % LT, oy = tid / LT;
    const int lbase = lx * T;
    const bool act = tid < NTHR;

    u64 accp[NACC][T];
#pragma unroll
    for (int p = 0; p < NACC; p++)
#pragma unroll
        for (int t = 0; t < T; t++) {
            if (C::EPI == 3) accp[p][t] = 0ull;
            else accp[p][t] = pack2(bias[o0 + oy * OTT + 2 * p],
                                    bias[o0 + oy * OTT + 2 * p + 1]);
        }

    float* wFull = sm + 2 * CHUNKF;                    // PIPE==2
    int* tokS = (int*)(sm + 2 * CHUNKF + (C::PIPE == 2 ? CIN * TILE_O : 0));  // EMB

    if (C::EMB) {
        for (int idx = tid; idx < WV; idx += BT) {
            int gl = l0 + idx;
            tokS[idx] = (gl < Lin) ? tok[b * Lin + gl] : 0;
        }
        __syncthreads();
    }
    if (C::PIPE == 2) {
        // one-time weight stage (transposed, contiguous 16B runs)
        const float* wbase = Wt + o0;
        for (int idx = tid; idx < CIN * TO4; idx += BT) {
            int r = idx / TO4, q = idx - r * TO4;
            cp16(&wFull[r * TILE_O + 4 * q], wbase + (size_t)r * Cout + 4 * q);
        }
    }

    conv_preload<C>(sm, in, tokS, Wt, 0, b, l0, o0, Lin, LinP, Cout, tid, BT);
    cp_commit();
    for (int ch = 0; ch < NCH; ch++) {
        float* cur = sm + (ch & 1) * CHUNKF;
        if (ch + 1 < NCH) {
            conv_preload<C>(sm + ((ch + 1) & 1) * CHUNKF, in, tokS, Wt, ch + 1, b, l0, o0, Lin, LinP, Cout, tid, BT);
            cp_commit();
            cp_wait1();
        } else {
            cp_wait0();
        }
        __syncthreads();
        if (act) {
            if (C::PIPE == 1)
                conv_compute<C>(cur, cur + CH * PITCH, accp, lbase, oy);
            else
                conv_compute<C>(cur, wFull + ch * CH * TILE_O, accp, lbase, oy);
        }
        __syncthreads();
    }

    if (act) {
#pragma unroll
        for (int p = 0; p < NACC; p++) {
            int olo = o0 + oy * OTT + 2 * p;
            if (C::EPI == 3) {
                float m0 = 0.f, m1 = 0.f;
                const float* g0 = gate + ((size_t)b * Cout + olo) * LoutP;
                const float* g1 = g0 + LoutP;
#pragma unroll
                for (int t = 0; t < T; t++) {
                    int l = l0 + lbase + t;
                    if (l >= Lout) continue;
                    float vlo, vhi;
                    unpack2(vlo, vhi, accp[p][t]);
                    vlo = 1.f / (1.f + __expf(-(vlo * scale + bias[olo])));
                    vhi = 1.f / (1.f + __expf(-(vhi * scale + bias[olo + 1])));
                    m0 = fmaxf(m0, g0[l] * (0.5f + vlo));
                    m1 = fmaxf(m1, g1[l] * (0.5f + vhi));
                }
#pragma unroll
                for (int s = LT / 2; s; s >>= 1) {
                    m0 = fmaxf(m0, __shfl_xor_sync(0xffffffffu, m0, s));
                    m1 = fmaxf(m1, __shfl_xor_sync(0xffffffffu, m1, s));
                }
                if (lx == 0) {
                    atomicMax((int*)&out[b * 320 + poff + olo], __float_as_int(m0));
                    atomicMax((int*)&out[b * 320 + poff + olo + 1], __float_as_int(m1));
                }
            } else {
#pragma unroll
                for (int t = 0; t < T; t++) {
                    int l = l0 + lbase + t;
                    if (l >= Lout) continue;
                    float vlo, vhi;
                    unpack2(vlo, vhi, accp[p][t]);
                    if (C::EPI == 0) { vlo = fmaxf(vlo, 0.f); vhi = fmaxf(vhi, 0.f); }
                    out[((size_t)b * Cout + olo) * LoutP + l] = vlo;
                    out[((size_t)b * Cout + olo + 1) * LoutP + l] = vhi;
                }
            }
        }
    }
}

// ---------------- dual conv kernel (protein blocks first, then drug blocks) ----------------
template <class CP, class CD>
__global__ void __launch_bounds__(128)
dual_conv(const float* __restrict__ inP, const int* __restrict__ tokP,
          const float* __restrict__ WtP, const float* __restrict__ bP, float* __restrict__ outP,
          const float* __restrict__ gateP,
          int LinP_, int LinPP, int LoutP_, int LoutPP, float scP, int gxP, int gyP,
          const float* __restrict__ inD, const int* __restrict__ tokD,
          const float* __restrict__ WtD, const float* __restrict__ bD, float* __restrict__ outD,
          const float* __restrict__ gateD,
          int LinD_, int LinPD, int LoutD_, int LoutPD, float scD, int gxD, int gyD)
{
    constexpr int SMF = CP::SMEMF > CD::SMEMF ? CP::SMEMF : CD::SMEMF;
    __shared__ __align__(16) float sm[SMF];
    int blk = blockIdx.x;
    int nP = gxP * gyP * NB;
    if (blk < nP) {
        int bx = blk % gxP; int r = blk / gxP;
        int by = r % gyP, bz = r / gyP;
        conv_body<CP>(sm, inP, tokP, WtP, bP, outP, gateP, 160,
                      LinP_, LinPP, LoutP_, LoutPP, gyP * CP::TILE_O,
                      scP, bx, by, bz, blockDim.x);
    } else {
        blk -= nP;
        int bx = blk % gxD; int r = blk / gxD;
        int by = r % gyD, bz = r / gyD;
        conv_body<CD>(sm, inD, tokD, WtD, bD, outD, gateD, 0,
                      LinD_, LinPD, LoutD_, LoutPD, gyD * CD::TILE_O,
                      scD, bx, by, bz, blockDim.x);
    }
}

// ---------------- interaction sums (pitched) ----------------
__global__ void interact_kernel(const float* __restrict__ datt, const float* __restrict__ patt,
                                float* __restrict__ Sd, float* __restrict__ Sp)
{
    int k = blockIdx.x, b = blockIdx.y;
    int t = threadIdx.x;
    __shared__ float dvs[D3L];
    __shared__ float red[8][D3L];

    const float* dv = datt + ((size_t)b * C3 + k) * D3P;
    const float* pv = patt + ((size_t)b * C3 + k) * P3P;
    float* SpRow = Sp + ((size_t)b * C3 + k) * P3P;

    if (t < D3L) dvs[t] = dv[t];
    __syncthreads();

    float dl[D3L];
#pragma unroll
    for (int d = 0; d < D3L; d++) dl[d] = dvs[d];
    float sdp[D3L];
#pragma unroll
    for (int d = 0; d < D3L; d++) sdp[d] = 0.f;

    for (int p = t; p < P3L; p += 256) {
        float pvv = pv[p];
        float sp = 0.f;
#pragma unroll
        for (int d = 0; d < D3L; d++) {
            float v = fmaxf(dl[d] + pvv, 0.f);
            sdp[d] += v;
            sp += v;
        }
        SpRow[p] = sp;
    }

    int warp = t >> 5, lane = t & 31;
#pragma unroll
    for (int d = 0; d < D3L; d++) {
        float v = sdp[d];
        v += __shfl_xor_sync(0xffffffffu, v, 16);
        v += __shfl_xor_sync(0xffffffffu, v, 8);
        v += __shfl_xor_sync(0xffffffffu, v, 4);
        v += __shfl_xor_sync(0xffffffffu, v, 2);
        v += __shfl_xor_sync(0xffffffffu, v, 1);
        if (lane == 0) red[warp][d] = v;
    }
    __syncthreads();
    if (t < D3L) {
        float s = 0.f;
#pragma unroll
        for (int w = 0; w < 8; w++) s += red[w][t];
        Sd[((size_t)b * C3 + k) * D3P + t] = s;
    }
}

// ---------------- fused 4-layer MLP head ----------------
__global__ void __launch_bounds__(1024)
mlp_kernel(const float* __restrict__ pairv,
           const float* __restrict__ fc1W, const float* __restrict__ fc1b,
           const float* __restrict__ fc2W, const float* __restrict__ fc2b,
           const float* __restrict__ fc3W, const float* __restrict__ fc3b,
           const float* __restrict__ outW, const float* __restrict__ outb,
           float* __restrict__ out)
{
    __shared__ float s0[320];
    __shared__ float h1s[1024];
    __shared__ float h2s[1024];
    __shared__ float h3s[512];
    int b = blockIdx.x, t = threadIdx.x;

    if (t < 320) s0[t] = pairv[b * 320 + t];
    __syncthreads();

    {
        const float4* Wo = (const float4*)(fc1W + (size_t)t * 320);
        float acc = fc1b[t];
#pragma unroll 8
        for (int i = 0; i < 80; i++) {
            float4 wv = Wo[i];
            const float* xv = &s0[4 * i];
            acc = fmaf(wv.x, xv[0], acc);
            acc = fmaf(wv.y, xv[1], acc);
            acc = fmaf(wv.z, xv[2], acc);
            acc = fmaf(wv.w, xv[3], acc);
        }
        h1s[t] = acc > 0.f ? acc : 0.01f * acc;
    }
    __syncthreads();

    {
        const float4* Wo = (const float4*)(fc2W + (size_t)t * 1024);
        float acc = fc2b[t];
#pragma unroll 8
        for (int i = 0; i < 256; i++) {
            float4 wv = Wo[i];
            const float* xv = &h1s[4 * i];
            acc = fmaf(wv.x, xv[0], acc);
            acc = fmaf(wv.y, xv[1], acc);
            acc = fmaf(wv.z, xv[2], acc);
            acc = fmaf(wv.w, xv[3], acc);
        }
        h2s[t] = acc > 0.f ? acc : 0.01f * acc;
    }
    __syncthreads();

    if (t < 512) {
        const float4* Wo = (const float4*)(fc3W + (size_t)t * 1024);
        float acc = fc3b[t];
#pragma unroll 8
        for (int i = 0; i < 256; i++) {
            float4 wv = Wo[i];
            const float* xv = &h2s[4 * i];
            acc = fmaf(wv.x, xv[0], acc);
            acc = fmaf(wv.y, xv[1], acc);
            acc = fmaf(wv.z, xv[2], acc);
            acc = fmaf(wv.w, xv[3], acc);
        }
        h3s[t] = acc > 0.f ? acc : 0.01f * acc;
    }
    __syncthreads();

    if (t < 64) {
        int o = t >> 5, lane = t & 31;
        const float* Wo = outW + (size_t)o * 512;
        float acc = 0.f;
#pragma unroll
        for (int i = 0; i < 16; i++)
            acc = fmaf(Wo[lane + 32 * i], h3s[lane + 32 * i], acc);
#pragma unroll
        for (int s = 16; s; s >>= 1)
            acc += __shfl_xor_sync(0xffffffffu, acc, s);
        if (lane == 0) out[b * 2 + o] = acc + outb[o];
    }
}

// ---------------- configs:  K, CIN, CH, TL, T, TO, OTT, EPI, EMB, PIPE ----------------
using CP1 = CC<4, 64, 16, 128, 4, 8, 2, 0, 1, 1>;   // protein conv1 (+emb)
using CD1 = CC<4, 64, 16, 64, 4, 8, 2, 0, 1, 1>;    // drug conv1 (+emb)
using CP2 = CC<8, 40, 8, 128, 4, 16, 4, 0, 0, 1>;   // protein conv2
using CD2 = CC<6, 40, 8, 64, 4, 16, 4, 0, 0, 1>;    // drug conv2
using CP3 = CC<12, 80, 8, 128, 4, 16, 4, 0, 0, 1>;  // protein conv3
using CD3 = CC<8, 80, 8, 64, 4, 16, 4, 0, 0, 1>;    // drug conv3
using CPp = CC<1, 160, 16, 128, 4, 16, 4, 1, 0, 2>; // protein proj
using CDp = CC<1, 160, 16, 64, 4, 16, 4, 1, 0, 2>;  // drug proj
using CPa = CC<1, 160, 16, 128, 4, 16, 4, 3, 0, 2>; // protein att_out+gate+pool
using CDa = CC<1, 160, 16, 64, 4, 16, 4, 3, 0, 2>;  // drug att_out+gate+pool

// ---------------- launch ----------------
extern "C" void kernel_launch(void* const* d_in, const int* in_sizes, int n_in,
                              void* d_out, int out_size)
{
    const int*   dtok = (const int*)d_in[0];
    const int*   ptok = (const int*)d_in[1];
    const float* demb = (const float*)d_in[2];
    const float* pemb = (const float*)d_in[3];
    const float* dW1 = (const float*)d_in[4],  *db1 = (const float*)d_in[5];
    const float* dW2 = (const float*)d_in[6],  *db2 = (const float*)d_in[7];
    const float* dW3 = (const float*)d_in[8],  *db3 = (const float*)d_in[9];
    const float* pW1 = (const float*)d_in[10], *pb1 = (const float*)d_in[11];
    const float* pW2 = (const float*)d_in[12], *pb2 = (const float*)d_in[13];
    const float* pW3 = (const float*)d_in[14], *pb3 = (const float*)d_in[15];
    const float* dattW = (const float*)d_in[16], *dattb = (const float*)d_in[17];
    const float* pattW = (const float*)d_in[18], *pattb = (const float*)d_in[19];
    const float* attW  = (const float*)d_in[20], *attb  = (const float*)d_in[21];
    const float* fc1W = (const float*)d_in[22], *fc1b = (const float*)d_in[23];
    const float* fc2W = (const float*)d_in[24], *fc2b = (const float*)d_in[25];
    const float* fc3W = (const float*)d_in[26], *fc3b = (const float*)d_in[27];
    const float* outW = (const float*)d_in[28], *outb = (const float*)d_in[29];
    float* out = (float*)d_out;

    float *d1, *d2, *dc, *p1, *p2, *pc;
    float *datt, *patt, *Sd, *Sp, *pairv, *wt;
    cudaGetSymbolAddress((void**)&d1, g_d1);
    cudaGetSymbolAddress((void**)&d2, g_d2);
    cudaGetSymbolAddress((void**)&dc, g_dc);
    cudaGetSymbolAddress((void**)&p1, g_p1);
    cudaGetSymbolAddress((void**)&p2, g_p2);
    cudaGetSymbolAddress((void**)&pc, g_pc);
    cudaGetSymbolAddress((void**)&datt, g_datt);
    cudaGetSymbolAddress((void**)&patt, g_patt);
    cudaGetSymbolAddress((void**)&Sd, g_Sd);
    cudaGetSymbolAddress((void**)&Sp, g_Sp);
    cudaGetSymbolAddress((void**)&pairv, g_pair);
    cudaGetSymbolAddress((void**)&wt, g_wt);

    // 0) weight pre-transpose (once per launch; consumed by all conv kernels)
    prep_w<<<dim3(64, 9), 128>>>(dW1, dW2, dW3, pW1, pW2, pW3, dattW, pattW, attW, wt);

    // conv1: P gx=10 gy=5 -> 800; D gx=1 gy=5 -> 80
    dual_conv<CP1, CD1><<<800 + 80, 128>>>(
        pemb, ptok, wt + OFF_pW1t, pb1, p1, 0, PLEN, PLEN, P1L, P1P, 0.f, 10, 5,
        demb, dtok, wt + OFF_dW1t, db1, d1, 0, DLEN, DLEN, D1L, D1P, 0.f, 1, 5);

    // conv2: P 800; D 80
    dual_conv<CP2, CD2><<<800 + 80, 128>>>(
        p1, 0, wt + OFF_pW2t, pb2, p2, 0, P1L, P1P, P2L, P2P, 0.f, 10, 5,
        d1, 0, wt + OFF_dW2t, db2, d2, 0, D1L, D1P, D2L, D2P, 0.f, 1, 5);

    // conv3: P gx=10 gy=10 -> 1600; D 160
    dual_conv<CP3, CD3><<<1600 + 160, 128>>>(
        p2, 0, wt + OFF_pW3t, pb3, pc, 0, P2L, P2P, P3L, P3P, 0.f, 10, 10,
        d2, 0, wt + OFF_dW3t, db3, dc, 0, D2L, D2P, D3L, D3P, 0.f, 1, 10);

    // attention projections: P 1600; D 160
    dual_conv<CPp, CDp><<<1600 + 160, 128>>>(
        pc, 0, wt + OFF_pattWt, pattb, patt, 0, P3L, P3P, P3L, P3P, 0.f, 10, 10,
        dc, 0, wt + OFF_dattWt, dattb, datt, 0, D3L, D3P, D3L, D3P, 0.f, 1, 10);

    // interaction sums
    interact_kernel<<<dim3(C3, NB), 256>>>(datt, patt, Sd, Sp);

    // zero the pooled pair vector (atomicMax target; values >= 0)
    cudaMemsetAsync(pairv, 0, NB * 320 * sizeof(float));

    // fused attention-output + gating + max-pool: writes pairv directly
    dual_conv<CPa, CDa><<<1600 + 160, 128>>>(
        Sp, 0, wt + OFF_attWt, attb, pairv, pc, P3L, P3P, P3L, P3P, 1.f / (float)D3L, 10, 10,
        Sd, 0, wt + OFF_attWt, attb, pairv, dc, D3L, D3P, D3L, D3P, 1.f / (float)P3L, 1, 10);

    // MLP head
    mlp_kernel<<<NB, 1024>>>(pairv, fc1W, fc1b, fc2W, fc2b, fc3W, fc3b, outW, outb, out);
}